// round 6
// baseline (speedup 1.0000x reference)
#include <cuda_runtime.h>
#include <math.h>

#define Bb   8
#define Dd   160
#define Nn   32768
#define Kk   589
#define KP   592                 // padded K (float4-aligned, pads are zero)
#define KPR  (KP * 8)            // padded bases/t1 batch stride
#define Rr   8
#define NT   128                 // big-pass tile width
#define NBLK 256                 // Nn / NT
#define XSS  132                 // x-tile smem row stride (words)
#define CTS  132                 // ct row stride (floats)
#define EPSV 1e-6f
#define DN   ((size_t)Dd * (size_t)Nn)
#define KR   (Kk * Rr)           // 4712
#define DR   (Dd * Rr)           // 1280
#define NTF  256
#define NBLKF 128

// ---------------- static device scratch ----------------
__device__ float g_E    [Dd * KP];
__device__ float g_Et   [Kk * Dd];
__device__ float g_EtE  [(size_t)Kk * KP];
__device__ float g_bases[Bb * KPR];
__device__ float g_t1   [Bb * KPR];
__device__ float g_ebp  [2 * Bb * DR];              // Eb split-K partials
__device__ float g_coef [(size_t)Bb * Nn * Rr];
__device__ float g_sxc  [(size_t)Bb * NBLK * DR];
__device__ float g_sctc [Bb * NBLK * 64];
__device__ float g_xcoef[Bb * DR];

// ---------------- packed f32x2 helpers ----------------
__device__ __forceinline__ unsigned long long pk2(float lo, float hi) {
    unsigned long long r;
    asm("mov.b64 %0, {%1, %2};" : "=l"(r) : "f"(lo), "f"(hi));
    return r;
}
__device__ __forceinline__ void upk2(unsigned long long v, float& lo, float& hi) {
    asm("mov.b64 {%0, %1}, %2;" : "=f"(lo), "=f"(hi) : "l"(v));
}
__device__ __forceinline__ unsigned long long fma2_(unsigned long long a,
                                                    unsigned long long b,
                                                    unsigned long long c) {
    unsigned long long d;
    asm("fma.rn.f32x2 %0, %1, %2, %3;" : "=l"(d) : "l"(a), "l"(b), "l"(c));
    return d;
}

// ---------------- build RBF estimator bank (+ transpose) ----------------
__global__ void k_build_E() {
    int d = blockIdx.x;
    for (int k = threadIdx.x; k < KP; k += blockDim.x) {
        float v = 0.f;
        if (k < Kk) {
            if (k == 588) {
                v = 1.0f;
            } else {
                float sig; int n;
                if      (k < 160) { sig = 6.0f;  n = k; }
                else if (k < 320) { sig = 8.0f;  n = k - 160; }
                else if (k < 400) { sig = 12.0f; n = (k - 320) * 2; }
                else if (k < 480) { sig = 15.0f; n = (k - 400) * 2; }
                else if (k < 534) { sig = 18.0f; n = (k - 480) * 3; }
                else              { sig = 24.0f; n = (k - 534) * 3; }
                float diff = (float)d - (float)n;
                v = expf(-0.5f * (diff * diff) / (2.0f * sig * sig));
            }
        }
        g_E[d * KP + k] = v;
        if (k < Kk) g_Et[k * Dd + d] = v;
    }
}

// ---------------- EtE = E^T E : grid(148), 4 rows/block ----------------
__global__ __launch_bounds__(256) void k_EtE() {
    __shared__ float se[Dd * 4];
    int i0 = blockIdx.x * 4;
    int t = threadIdx.x;
    for (int idx = t; idx < Dd * 4; idx += 256) {
        int d = idx >> 2, i = idx & 3;
        int ki = i0 + i;
        se[idx] = (ki < Kk) ? g_Et[ki * Dd + d] : 0.f;
    }
    __syncthreads();
    int j0 = t, j1 = t + 256, j2 = t + 512;
    bool has2 = (j2 < KP);
    float a0[4] = {0,0,0,0}, a1[4] = {0,0,0,0}, a2[4] = {0,0,0,0};
    #pragma unroll 4
    for (int d = 0; d < Dd; d++) {
        float e0 = g_E[d * KP + j0];
        float e1 = g_E[d * KP + j1];
        float e2 = has2 ? g_E[d * KP + j2] : 0.f;
        #pragma unroll
        for (int i = 0; i < 4; i++) {
            float s = se[d * 4 + i];
            a0[i] = fmaf(e0, s, a0[i]);
            a1[i] = fmaf(e1, s, a1[i]);
            a2[i] = fmaf(e2, s, a2[i]);
        }
    }
    #pragma unroll
    for (int i = 0; i < 4; i++) {
        int row = i0 + i;
        if (row < Kk) {
            g_EtE[(size_t)row * KP + j0] = a0[i];
            g_EtE[(size_t)row * KP + j1] = a1[i];
            if (has2) g_EtE[(size_t)row * KP + j2] = a2[i];
        }
    }
}

// ---------------- L2-normalize bases_init (+ zero pads) ----------------
__global__ void k_norm(const float* __restrict__ bin) {
    int b = blockIdx.x;
    int r = threadIdx.x >> 5;
    int l = threadIdx.x & 31;
    float ss = 0.f;
    for (int k = l; k < Kk; k += 32) {
        float v = bin[(b * Kk + k) * Rr + r];
        ss += v * v;
    }
    #pragma unroll
    for (int o = 16; o; o >>= 1) ss += __shfl_xor_sync(0xffffffffu, ss, o);
    float nrm = fmaxf(sqrtf(ss), 1e-12f);
    for (int k = l; k < Kk; k += 32)
        g_bases[b * KPR + k * Rr + r] = bin[(b * Kk + k) * Rr + r] / nrm;
    if (threadIdx.x < KPR - KR)
        g_bases[b * KPR + KR + threadIdx.x] = 0.f;
}

// ---------------- Eb partials: grid(40, 2, Bb), 8 lanes per output ----------------
__global__ __launch_bounds__(256) void k_EbG2() {
    int t = threadIdx.x;
    int q = blockIdx.y, b = blockIdx.z;
    int out = t >> 3, kg = t & 7;
    int idx = blockIdx.x * 32 + out;               // 0..1279
    int d = idx >> 3, r = idx & 7;
    const float* Erow = g_E + d * KP + q * 296 + kg;
    const float* brow = g_bases + b * KPR + (q * 296 + kg) * 8 + r;
    float acc0 = 0.f, acc1 = 0.f;
    #pragma unroll
    for (int i = 0; i < 36; i += 2) {
        acc0 = fmaf(Erow[8 * i],       brow[64 * i],       acc0);
        acc1 = fmaf(Erow[8 * (i + 1)], brow[64 * (i + 1)], acc1);
    }
    acc0 = fmaf(Erow[8 * 36], brow[64 * 36], acc0);
    float acc = acc0 + acc1;
    acc += __shfl_down_sync(0xffffffffu, acc, 4);
    acc += __shfl_down_sync(0xffffffffu, acc, 2);
    acc += __shfl_down_sync(0xffffffffu, acc, 1);
    if (kg == 0) g_ebp[(q * Bb + b) * DR + idx] = acc;
}

// ---------------- fused big pass (NT=128, 2 CTAs/SM) ----------------
template<int INIT>
__global__ __launch_bounds__(NT) void k_pass(const float* __restrict__ x) {
    extern __shared__ float sm[];
    float* xs  = sm;                               // [160][132]
    float* ct  = sm + Dd * XSS;                    // [8][132]
    float* ebs = ct + Rr * CTS;                    // [1280]
    float* gs  = ebs + DR;                         // [64]

    int t = threadIdx.x;
    int blk = blockIdx.x, b = blockIdx.y;
    int n0 = blk * NT;
    const float* xb = x + (size_t)b * DN + n0 + t;

    for (int i = t; i < DR; i += NT)
        ebs[i] = g_ebp[b * DR + i] + g_ebp[(Bb + b) * DR + i];
    __syncthreads();

    if (t < 64) {
        int r = t >> 3, s = t & 7;
        float a = 0.f;
        #pragma unroll 8
        for (int d = 0; d < Dd; d++) a = fmaf(ebs[d * 8 + r], ebs[d * 8 + s], a);
        gs[t] = a;
    }

    // pass 1: stage tile + L[r] = sum_d x[d][n]*Eb[d][r], MLP-32 loads
    unsigned long long L2a[4] = {0ull, 0ull, 0ull, 0ull};
    #pragma unroll 1
    for (int d0 = 0; d0 < Dd; d0 += 32) {
        float xv[32];
        #pragma unroll
        for (int i = 0; i < 32; i++) xv[i] = __ldg(xb + (size_t)(d0 + i) * Nn);
        #pragma unroll
        for (int i = 0; i < 32; i++) {
            int d = d0 + i;
            xs[d * XSS + t] = xv[i];
            unsigned long long x2 = pk2(xv[i], xv[i]);
            const ulonglong2* ep = (const ulonglong2*)(ebs + d * 8);
            ulonglong2 e0 = ep[0], e1 = ep[1];
            L2a[0] = fma2_(x2, e0.x, L2a[0]);
            L2a[1] = fma2_(x2, e0.y, L2a[1]);
            L2a[2] = fma2_(x2, e1.x, L2a[2]);
            L2a[3] = fma2_(x2, e1.y, L2a[3]);
        }
    }
    __syncthreads();

    float L[8];
    upk2(L2a[0], L[0], L[1]); upk2(L2a[1], L[2], L[3]);
    upk2(L2a[2], L[4], L[5]); upk2(L2a[3], L[6], L[7]);

    int n = n0 + t;
    float c_old[8];
    if (INIT) {
        float m = L[0];
        #pragma unroll
        for (int i = 1; i < 8; i++) m = fmaxf(m, L[i]);
        float ps = 0.f;
        #pragma unroll
        for (int i = 0; i < 8; i++) { c_old[i] = expf(L[i] - m); ps += c_old[i]; }
        float inv = 1.0f / ps;
        #pragma unroll
        for (int i = 0; i < 8; i++) c_old[i] *= inv;
    } else {
        const float4* cg = (const float4*)(g_coef + ((size_t)b * Nn + n) * 8);
        float4 a = cg[0], c = cg[1];
        c_old[0]=a.x; c_old[1]=a.y; c_old[2]=a.z; c_old[3]=a.w;
        c_old[4]=c.x; c_old[5]=c.y; c_old[6]=c.z; c_old[7]=c.w;
    }

    float c1[8];
    #pragma unroll
    for (int r = 0; r < 8; r++) {
        float den = 0.f;
        #pragma unroll
        for (int s = 0; s < 8; s++) den = fmaf(c_old[s], gs[s * 8 + r], den);
        c1[r] = c_old[r] * L[r] / (den + EPSV);
    }

    float4* cgw = (float4*)(g_coef + ((size_t)b * Nn + n) * 8);
    cgw[0] = make_float4(c1[0], c1[1], c1[2], c1[3]);
    cgw[1] = make_float4(c1[4], c1[5], c1[6], c1[7]);
    #pragma unroll
    for (int r = 0; r < 8; r++) ct[r * CTS + t] = c1[r];
    __syncthreads();

    // pass 2: xcoef partials — n-pair packed fma2, zero pk2 movs.
    // thread = (r = t&7, db = t>>3); d = db + 16j, j<10
    {
        int r  = t & 7;
        int db = t >> 3;
        unsigned long long acc2[10];
        #pragma unroll
        for (int j = 0; j < 10; j++) acc2[j] = 0ull;
        #pragma unroll 2
        for (int n4 = 0; n4 < NT / 4; n4++) {
            ulonglong2 cc = *(const ulonglong2*)(ct + r * CTS + n4 * 4);
            #pragma unroll
            for (int j = 0; j < 10; j++) {
                ulonglong2 xx = *(const ulonglong2*)(xs + (db + 16 * j) * XSS + n4 * 4);
                acc2[j] = fma2_(xx.x, cc.x, acc2[j]);
                acc2[j] = fma2_(xx.y, cc.y, acc2[j]);
            }
        }
        float* outp = g_sxc + (size_t)(b * NBLK + blk) * DR;
        #pragma unroll
        for (int j = 0; j < 10; j++) {
            float lo, hi; upk2(acc2[j], lo, hi);
            outp[(db + 16 * j) * 8 + r] = lo + hi;
        }
    }

    // pass 2b: ctc block partials (threads 0..63)
    if (t < 64) {
        int r = t >> 3, s = t & 7;
        float acc = 0.f;
        #pragma unroll 4
        for (int i = 0; i < NT / 2; i++) {
            float2 a = *(const float2*)(ct + r * CTS + 2 * i);
            float2 bq = *(const float2*)(ct + s * CTS + 2 * i);
            acc = fmaf(a.x, bq.x, acc);
            acc = fmaf(a.y, bq.y, acc);
        }
        g_sctc[(size_t)(b * NBLK + blk) * 64 + t] = acc;
    }
}

// ---------------- glue A: grid(6,B). bx<5: reduce x@coef; bx==5: ctc + t1 ----------------
__global__ void k_glueA() {
    __shared__ float sc[64];
    __shared__ float spart[256];
    int bx = blockIdx.x, b = blockIdx.y, t = threadIdx.x;
    if (bx < 5) {
        int o = bx * 256 + t;
        const float* p = g_sxc + (size_t)b * NBLK * DR + o;
        float a0 = 0, a1 = 0, a2 = 0, a3 = 0;
        #pragma unroll 2
        for (int blk = 0; blk < NBLK; blk += 4) {
            a0 += p[(size_t)(blk + 0) * DR];
            a1 += p[(size_t)(blk + 1) * DR];
            a2 += p[(size_t)(blk + 2) * DR];
            a3 += p[(size_t)(blk + 3) * DR];
        }
        g_xcoef[b * DR + o] = (a0 + a1) + (a2 + a3);
        return;
    }
    {
        int o = t & 63, q = t >> 6;
        const float* p = g_sctc + (size_t)b * NBLK * 64 + o;
        float acc = 0.f;
        #pragma unroll 4
        for (int blk = q * 64; blk < q * 64 + 64; blk++) acc += p[blk * 64];
        spart[t] = acc;
    }
    __syncthreads();
    if (t < 64) sc[t] = (spart[t] + spart[t + 64]) + (spart[t + 128] + spart[t + 192]);
    __syncthreads();
    const float* bs = g_bases + b * KPR;
    float* t1 = g_t1 + b * KPR;
    for (int idx = t; idx < KR; idx += 256) {
        int k = idx >> 3, r = idx & 7;
        float a = 0.f;
        #pragma unroll
        for (int s = 0; s < 8; s++) a = fmaf(bs[k * 8 + s], sc[s * 8 + r], a);
        t1[idx] = a;
    }
}

// ---------------- glue B: bases *= (E^T xcoef) / (EtE @ t1 + eps) ----------------
__global__ __launch_bounds__(256) void k_glueB() {
    __shared__ float sx[DR];
    __shared__ __align__(16) float st1[KP * Rr];
    int b = blockIdx.y, t = threadIdx.x;
    for (int i = t; i < DR; i += 256) sx[i] = g_xcoef[b * DR + i];
    for (int i = t; i < KP * Rr; i += 256) st1[i] = g_t1[b * KPR + i];
    __syncthreads();
    int idx = blockIdx.x * 256 + t;
    if (idx >= KR) return;
    int k = idx >> 3, r = idx & 7;
    const float4* et = (const float4*)(g_Et + k * Dd);
    float n0 = 0.f, n1 = 0.f, n2 = 0.f, n3 = 0.f;
    #pragma unroll 8
    for (int i = 0; i < Dd / 4; i++) {
        float4 e = et[i];
        n0 = fmaf(e.x, sx[(4 * i + 0) * 8 + r], n0);
        n1 = fmaf(e.y, sx[(4 * i + 1) * 8 + r], n1);
        n2 = fmaf(e.z, sx[(4 * i + 2) * 8 + r], n2);
        n3 = fmaf(e.w, sx[(4 * i + 3) * 8 + r], n3);
    }
    float num = (n0 + n1) + (n2 + n3);
    const float4* ee = (const float4*)(g_EtE + (size_t)k * KP);
    float d0 = 0.f, d1 = 0.f, d2 = 0.f, d3 = 0.f;
    #pragma unroll 8
    for (int i = 0; i < KP / 4; i++) {
        float4 v = ee[i];
        d0 = fmaf(v.x, st1[(4 * i + 0) * 8 + r], d0);
        d1 = fmaf(v.y, st1[(4 * i + 1) * 8 + r], d1);
        d2 = fmaf(v.z, st1[(4 * i + 2) * 8 + r], d2);
        d3 = fmaf(v.w, st1[(4 * i + 3) * 8 + r], d3);
    }
    float den = (d0 + d1) + (d2 + d3);
    g_bases[b * KPR + idx] *= num / (den + EPSV);
}

// ---------------- final coef update + reconstruction ----------------
__global__ __launch_bounds__(NTF) void k_final(const float* __restrict__ x,
                                               float* __restrict__ out) {
    __shared__ __align__(16) float ebs[DR];
    __shared__ float gs[64];
    int t = threadIdx.x, blk = blockIdx.x, b = blockIdx.y;
    int n0 = blk * NTF;
    for (int i = t; i < DR; i += NTF)
        ebs[i] = g_ebp[b * DR + i] + g_ebp[(Bb + b) * DR + i];
    __syncthreads();
    if (t < 64) {
        int r = t >> 3, s = t & 7;
        float a = 0.f;
        #pragma unroll 8
        for (int d = 0; d < Dd; d++) a = fmaf(ebs[d * 8 + r], ebs[d * 8 + s], a);
        gs[t] = a;
    }

    const float* xb = x + (size_t)b * DN + n0 + t;
    unsigned long long L2a[4] = {0ull, 0ull, 0ull, 0ull};
    #pragma unroll 1
    for (int d0 = 0; d0 < Dd; d0 += 32) {
        float xv[32];
        #pragma unroll
        for (int i = 0; i < 32; i++) xv[i] = __ldg(xb + (size_t)(d0 + i) * Nn);
        #pragma unroll
        for (int i = 0; i < 32; i++) {
            unsigned long long x2 = pk2(xv[i], xv[i]);
            const ulonglong2* ep = (const ulonglong2*)(ebs + (d0 + i) * 8);
            ulonglong2 e0 = ep[0], e1 = ep[1];
            L2a[0] = fma2_(x2, e0.x, L2a[0]);
            L2a[1] = fma2_(x2, e0.y, L2a[1]);
            L2a[2] = fma2_(x2, e1.x, L2a[2]);
            L2a[3] = fma2_(x2, e1.y, L2a[3]);
        }
    }
    __syncthreads();

    float L[8];
    upk2(L2a[0], L[0], L[1]); upk2(L2a[1], L[2], L[3]);
    upk2(L2a[2], L[4], L[5]); upk2(L2a[3], L[6], L[7]);

    int n = n0 + t;
    const float4* cg = (const float4*)(g_coef + ((size_t)b * Nn + n) * 8);
    float4 a = cg[0], c = cg[1];
    float c_old[8] = {a.x, a.y, a.z, a.w, c.x, c.y, c.z, c.w};

    float c1[8];
    #pragma unroll
    for (int r = 0; r < 8; r++) {
        float den = 0.f;
        #pragma unroll
        for (int s = 0; s < 8; s++) den = fmaf(c_old[s], gs[s * 8 + r], den);
        c1[r] = c_old[r] * L[r] / (den + EPSV);
    }

    float* ob = out + (size_t)b * DN + n0 + t;
    #pragma unroll 4
    for (int d = 0; d < Dd; d++) {
        const float4* ep = (const float4*)(ebs + d * 8);
        float4 e0 = ep[0], e1 = ep[1];
        float v = e0.x * c1[0] + e0.y * c1[1] + e0.z * c1[2] + e0.w * c1[3]
                + e1.x * c1[4] + e1.y * c1[5] + e1.z * c1[6] + e1.w * c1[7];
        ob[(size_t)d * Nn] = v;
    }
}

// ---------------- launch ----------------
extern "C" void kernel_launch(void* const* d_in, const int* in_sizes, int n_in,
                              void* d_out, int out_size) {
    const float* x = (const float*)d_in[0];
    const float* binit = (const float*)d_in[1];
    float* out = (float*)d_out;

    const int PS = (Dd * XSS + Rr * CTS + DR + 64) * (int)sizeof(float);
    cudaFuncSetAttribute(k_pass<1>, cudaFuncAttributeMaxDynamicSharedMemorySize, PS);
    cudaFuncSetAttribute(k_pass<0>, cudaFuncAttributeMaxDynamicSharedMemorySize, PS);

    // Launch order chosen so index 3 (ncu snapshot) is the dominant k_pass.
    k_build_E<<<Dd, 256>>>();                       // 0
    k_norm<<<Bb, 256>>>(binit);                     // 1
    k_EbG2<<<dim3(40, 2, Bb), 256>>>();             // 2
    k_pass<1><<<dim3(NBLK, Bb), NT, PS>>>(x);       // 3  <- profiled
    k_EtE<<<148, 256>>>();                          // 4 (needed before first glueB)
    k_glueA<<<dim3(6, Bb), 256>>>();
    k_glueB<<<dim3(19, Bb), 256>>>();
    k_EbG2<<<dim3(40, 2, Bb), 256>>>();

    for (int s = 1; s < 4; s++) {
        k_pass<0><<<dim3(NBLK, Bb), NT, PS>>>(x);
        k_glueA<<<dim3(6, Bb), 256>>>();
        k_glueB<<<dim3(19, Bb), 256>>>();
        k_EbG2<<<dim3(40, 2, Bb), 256>>>();
    }
    k_final<<<dim3(NBLKF, Bb), NTF>>>(x, out);
}

// round 7
// speedup vs baseline: 1.0655x; 1.0655x over previous
#include <cuda_runtime.h>
#include <math.h>

#define Bb   8
#define Dd   160
#define Nn   32768
#define Kk   589
#define KP   592                 // padded K (float4-aligned, pads are zero)
#define KPR  (KP * 8)            // padded bases/t1 batch stride
#define Rr   8
#define NT   128                 // big-pass tile width
#define NBLK 256                 // Nn / NT
#define XSS  132                 // x-tile smem row stride (words)
#define CTS  132                 // ct row stride (floats)
#define EPSV 1e-6f
#define DN   ((size_t)Dd * (size_t)Nn)
#define KR   (Kk * Rr)           // 4712
#define DR   (Dd * Rr)           // 1280
#define NTF  256
#define NBLKF 128

// ---------------- static device scratch ----------------
__device__ float g_E    [Dd * KP];
__device__ float g_Et   [Kk * Dd];
__device__ float g_EtE  [(size_t)Kk * KP];
__device__ float g_bases[Bb * KPR];
__device__ float g_t1   [Bb * KPR];
__device__ float g_ebp  [2 * Bb * DR];              // Eb split-K partials
__device__ float g_coef [(size_t)Bb * Nn * Rr];
__device__ float g_sxc  [(size_t)Bb * NBLK * DR];
__device__ float g_sctc [Bb * NBLK * 64];
__device__ float g_xcoef[Bb * DR];

// ---------------- packed f32x2 helpers ----------------
__device__ __forceinline__ unsigned long long pk2(float lo, float hi) {
    unsigned long long r;
    asm("mov.b64 %0, {%1, %2};" : "=l"(r) : "f"(lo), "f"(hi));
    return r;
}
__device__ __forceinline__ void upk2(unsigned long long v, float& lo, float& hi) {
    asm("mov.b64 {%0, %1}, %2;" : "=f"(lo), "=f"(hi) : "l"(v));
}
__device__ __forceinline__ unsigned long long fma2_(unsigned long long a,
                                                    unsigned long long b,
                                                    unsigned long long c) {
    unsigned long long d;
    asm("fma.rn.f32x2 %0, %1, %2, %3;" : "=l"(d) : "l"(a), "l"(b), "l"(c));
    return d;
}

// ---------------- build RBF estimator bank (+ transpose) ----------------
__global__ void k_build_E() {
    int d = blockIdx.x;
    for (int k = threadIdx.x; k < KP; k += blockDim.x) {
        float v = 0.f;
        if (k < Kk) {
            if (k == 588) {
                v = 1.0f;
            } else {
                float sig; int n;
                if      (k < 160) { sig = 6.0f;  n = k; }
                else if (k < 320) { sig = 8.0f;  n = k - 160; }
                else if (k < 400) { sig = 12.0f; n = (k - 320) * 2; }
                else if (k < 480) { sig = 15.0f; n = (k - 400) * 2; }
                else if (k < 534) { sig = 18.0f; n = (k - 480) * 3; }
                else              { sig = 24.0f; n = (k - 534) * 3; }
                float diff = (float)d - (float)n;
                v = expf(-0.5f * (diff * diff) / (2.0f * sig * sig));
            }
        }
        g_E[d * KP + k] = v;
        if (k < Kk) g_Et[k * Dd + d] = v;
    }
}

// ---------------- EtE = E^T E : grid(148), 4 rows/block ----------------
__global__ __launch_bounds__(256) void k_EtE() {
    __shared__ float se[Dd * 4];
    int i0 = blockIdx.x * 4;
    int t = threadIdx.x;
    for (int idx = t; idx < Dd * 4; idx += 256) {
        int d = idx >> 2, i = idx & 3;
        int ki = i0 + i;
        se[idx] = (ki < Kk) ? g_Et[ki * Dd + d] : 0.f;
    }
    __syncthreads();
    int j0 = t, j1 = t + 256, j2 = t + 512;
    bool has2 = (j2 < KP);
    float a0[4] = {0,0,0,0}, a1[4] = {0,0,0,0}, a2[4] = {0,0,0,0};
    #pragma unroll 4
    for (int d = 0; d < Dd; d++) {
        float e0 = g_E[d * KP + j0];
        float e1 = g_E[d * KP + j1];
        float e2 = has2 ? g_E[d * KP + j2] : 0.f;
        #pragma unroll
        for (int i = 0; i < 4; i++) {
            float s = se[d * 4 + i];
            a0[i] = fmaf(e0, s, a0[i]);
            a1[i] = fmaf(e1, s, a1[i]);
            a2[i] = fmaf(e2, s, a2[i]);
        }
    }
    #pragma unroll
    for (int i = 0; i < 4; i++) {
        int row = i0 + i;
        if (row < Kk) {
            g_EtE[(size_t)row * KP + j0] = a0[i];
            g_EtE[(size_t)row * KP + j1] = a1[i];
            if (has2) g_EtE[(size_t)row * KP + j2] = a2[i];
        }
    }
}

// ---------------- L2-normalize bases_init (+ zero pads) ----------------
__global__ void k_norm(const float* __restrict__ bin) {
    int b = blockIdx.x;
    int r = threadIdx.x >> 5;
    int l = threadIdx.x & 31;
    float ss = 0.f;
    for (int k = l; k < Kk; k += 32) {
        float v = bin[(b * Kk + k) * Rr + r];
        ss += v * v;
    }
    #pragma unroll
    for (int o = 16; o; o >>= 1) ss += __shfl_xor_sync(0xffffffffu, ss, o);
    float nrm = fmaxf(sqrtf(ss), 1e-12f);
    for (int k = l; k < Kk; k += 32)
        g_bases[b * KPR + k * Rr + r] = bin[(b * Kk + k) * Rr + r] / nrm;
    if (threadIdx.x < KPR - KR)
        g_bases[b * KPR + KR + threadIdx.x] = 0.f;
}

// ---------------- Eb partials: grid(40, 2, Bb), 8 lanes per output ----------------
__global__ __launch_bounds__(256) void k_EbG2() {
    int t = threadIdx.x;
    int q = blockIdx.y, b = blockIdx.z;
    int out = t >> 3, kg = t & 7;
    int idx = blockIdx.x * 32 + out;               // 0..1279
    int d = idx >> 3, r = idx & 7;
    const float* Erow = g_E + d * KP + q * 296 + kg;
    const float* brow = g_bases + b * KPR + (q * 296 + kg) * 8 + r;
    float acc0 = 0.f, acc1 = 0.f;
    #pragma unroll
    for (int i = 0; i < 36; i += 2) {
        acc0 = fmaf(Erow[8 * i],       brow[64 * i],       acc0);
        acc1 = fmaf(Erow[8 * (i + 1)], brow[64 * (i + 1)], acc1);
    }
    acc0 = fmaf(Erow[8 * 36], brow[64 * 36], acc0);
    float acc = acc0 + acc1;
    acc += __shfl_down_sync(0xffffffffu, acc, 4);
    acc += __shfl_down_sync(0xffffffffu, acc, 2);
    acc += __shfl_down_sync(0xffffffffu, acc, 1);
    if (kg == 0) g_ebp[(q * Bb + b) * DR + idx] = acc;
}

// ---------------- fused big pass (NT=128, 2 CTAs/SM) ----------------
template<int INIT>
__global__ __launch_bounds__(NT) void k_pass(const float* __restrict__ x) {
    extern __shared__ float sm[];
    float* xs  = sm;                               // [160][132]
    float* ct  = sm + Dd * XSS;                    // [8][132]
    float* ebs = ct + Rr * CTS;                    // [1280]
    float* gs  = ebs + DR;                         // [64]

    int t = threadIdx.x;
    int blk = blockIdx.x, b = blockIdx.y;
    int n0 = blk * NT;
    const float* xb = x + (size_t)b * DN + n0 + t;

    for (int i = t; i < DR; i += NT)
        ebs[i] = g_ebp[b * DR + i] + g_ebp[(Bb + b) * DR + i];
    __syncthreads();

    if (t < 64) {
        int r = t >> 3, s = t & 7;
        float a = 0.f;
        #pragma unroll 8
        for (int d = 0; d < Dd; d++) a = fmaf(ebs[d * 8 + r], ebs[d * 8 + s], a);
        gs[t] = a;
    }

    // pass 1: stage tile + L[r] = sum_d x[d][n]*Eb[d][r], MLP-16
    unsigned long long L2a[4] = {0ull, 0ull, 0ull, 0ull};
    #pragma unroll 1
    for (int d0 = 0; d0 < Dd; d0 += 16) {
        float xv[16];
        #pragma unroll
        for (int i = 0; i < 16; i++) xv[i] = __ldg(xb + (size_t)(d0 + i) * Nn);
        #pragma unroll
        for (int i = 0; i < 16; i++) {
            int d = d0 + i;
            xs[d * XSS + t] = xv[i];
            unsigned long long x2 = pk2(xv[i], xv[i]);
            const ulonglong2* ep = (const ulonglong2*)(ebs + d * 8);
            ulonglong2 e0 = ep[0], e1 = ep[1];
            L2a[0] = fma2_(x2, e0.x, L2a[0]);
            L2a[1] = fma2_(x2, e0.y, L2a[1]);
            L2a[2] = fma2_(x2, e1.x, L2a[2]);
            L2a[3] = fma2_(x2, e1.y, L2a[3]);
        }
    }
    __syncthreads();

    float L[8];
    upk2(L2a[0], L[0], L[1]); upk2(L2a[1], L[2], L[3]);
    upk2(L2a[2], L[4], L[5]); upk2(L2a[3], L[6], L[7]);

    int n = n0 + t;
    float c_old[8];
    if (INIT) {
        float m = L[0];
        #pragma unroll
        for (int i = 1; i < 8; i++) m = fmaxf(m, L[i]);
        float ps = 0.f;
        #pragma unroll
        for (int i = 0; i < 8; i++) { c_old[i] = expf(L[i] - m); ps += c_old[i]; }
        float inv = 1.0f / ps;
        #pragma unroll
        for (int i = 0; i < 8; i++) c_old[i] *= inv;
    } else {
        const float4* cg = (const float4*)(g_coef + ((size_t)b * Nn + n) * 8);
        float4 a = cg[0], c = cg[1];
        c_old[0]=a.x; c_old[1]=a.y; c_old[2]=a.z; c_old[3]=a.w;
        c_old[4]=c.x; c_old[5]=c.y; c_old[6]=c.z; c_old[7]=c.w;
    }

    float c1[8];
    #pragma unroll
    for (int r = 0; r < 8; r++) {
        float den = 0.f;
        #pragma unroll
        for (int s = 0; s < 8; s++) den = fmaf(c_old[s], gs[s * 8 + r], den);
        c1[r] = c_old[r] * L[r] / (den + EPSV);
    }

    float4* cgw = (float4*)(g_coef + ((size_t)b * Nn + n) * 8);
    cgw[0] = make_float4(c1[0], c1[1], c1[2], c1[3]);
    cgw[1] = make_float4(c1[4], c1[5], c1[6], c1[7]);
    #pragma unroll
    for (int r = 0; r < 8; r++) ct[r * CTS + t] = c1[r];
    __syncthreads();

    // pass 2: xcoef partials — rpt=2: thread = (r-pair p, db); 5 rows, 2 r each
    {
        int p  = t & 3;                  // r-pair: r = 2p, 2p+1
        int db = t >> 2;                 // 0..31; rows db + 32j, j<5
        unsigned long long accA[5], accB[5];
        #pragma unroll
        for (int j = 0; j < 5; j++) { accA[j] = 0ull; accB[j] = 0ull; }
        #pragma unroll 2
        for (int n4 = 0; n4 < NT / 4; n4++) {
            ulonglong2 c0 = *(const ulonglong2*)(ct + (2 * p)     * CTS + n4 * 4);
            ulonglong2 c1v = *(const ulonglong2*)(ct + (2 * p + 1) * CTS + n4 * 4);
            #pragma unroll
            for (int j = 0; j < 5; j++) {
                ulonglong2 xx = *(const ulonglong2*)(xs + (db + 32 * j) * XSS + n4 * 4);
                accA[j] = fma2_(xx.x, c0.x, accA[j]);
                accA[j] = fma2_(xx.y, c0.y, accA[j]);
                accB[j] = fma2_(xx.x, c1v.x, accB[j]);
                accB[j] = fma2_(xx.y, c1v.y, accB[j]);
            }
        }
        float* outp = g_sxc + (size_t)(b * NBLK + blk) * DR;
        #pragma unroll
        for (int j = 0; j < 5; j++) {
            float la, ha, lb, hb;
            upk2(accA[j], la, ha);
            upk2(accB[j], lb, hb);
            *(float2*)(outp + (db + 32 * j) * 8 + 2 * p) = make_float2(la + ha, lb + hb);
        }
    }

    // pass 2b: ctc block partials (threads 0..63)
    if (t < 64) {
        int r = t >> 3, s = t & 7;
        float acc = 0.f;
        #pragma unroll 4
        for (int i = 0; i < NT / 2; i++) {
            float2 a = *(const float2*)(ct + r * CTS + 2 * i);
            float2 bq = *(const float2*)(ct + s * CTS + 2 * i);
            acc = fmaf(a.x, bq.x, acc);
            acc = fmaf(a.y, bq.y, acc);
        }
        g_sctc[(size_t)(b * NBLK + blk) * 64 + t] = acc;
    }
}

// ---------------- glue A: grid(6,B). bx<5: reduce x@coef; bx==5: ctc + t1 ----------------
__global__ void k_glueA() {
    __shared__ float sc[64];
    __shared__ float spart[256];
    int bx = blockIdx.x, b = blockIdx.y, t = threadIdx.x;
    if (bx < 5) {
        int o = bx * 256 + t;
        const float* p = g_sxc + (size_t)b * NBLK * DR + o;
        float a0 = 0, a1 = 0, a2 = 0, a3 = 0;
        #pragma unroll 2
        for (int blk = 0; blk < NBLK; blk += 4) {
            a0 += p[(size_t)(blk + 0) * DR];
            a1 += p[(size_t)(blk + 1) * DR];
            a2 += p[(size_t)(blk + 2) * DR];
            a3 += p[(size_t)(blk + 3) * DR];
        }
        g_xcoef[b * DR + o] = (a0 + a1) + (a2 + a3);
        return;
    }
    {
        int o = t & 63, q = t >> 6;
        const float* p = g_sctc + (size_t)b * NBLK * 64 + o;
        float acc = 0.f;
        #pragma unroll 4
        for (int blk = q * 64; blk < q * 64 + 64; blk++) acc += p[blk * 64];
        spart[t] = acc;
    }
    __syncthreads();
    if (t < 64) sc[t] = (spart[t] + spart[t + 64]) + (spart[t + 128] + spart[t + 192]);
    __syncthreads();
    const float* bs = g_bases + b * KPR;
    float* t1 = g_t1 + b * KPR;
    for (int idx = t; idx < KR; idx += 256) {
        int k = idx >> 3, r = idx & 7;
        float a = 0.f;
        #pragma unroll
        for (int s = 0; s < 8; s++) a = fmaf(bs[k * 8 + s], sc[s * 8 + r], a);
        t1[idx] = a;
    }
}

// ---------------- glue B: bases *= (E^T xcoef) / (EtE @ t1 + eps) ----------------
__global__ __launch_bounds__(256) void k_glueB() {
    __shared__ float sx[DR];
    __shared__ __align__(16) float st1[KP * Rr];
    int b = blockIdx.y, t = threadIdx.x;
    for (int i = t; i < DR; i += 256) sx[i] = g_xcoef[b * DR + i];
    for (int i = t; i < KP * Rr; i += 256) st1[i] = g_t1[b * KPR + i];
    __syncthreads();
    int idx = blockIdx.x * 256 + t;
    if (idx >= KR) return;
    int k = idx >> 3, r = idx & 7;
    const float4* et = (const float4*)(g_Et + k * Dd);
    float n0 = 0.f, n1 = 0.f, n2 = 0.f, n3 = 0.f;
    #pragma unroll 8
    for (int i = 0; i < Dd / 4; i++) {
        float4 e = et[i];
        n0 = fmaf(e.x, sx[(4 * i + 0) * 8 + r], n0);
        n1 = fmaf(e.y, sx[(4 * i + 1) * 8 + r], n1);
        n2 = fmaf(e.z, sx[(4 * i + 2) * 8 + r], n2);
        n3 = fmaf(e.w, sx[(4 * i + 3) * 8 + r], n3);
    }
    float num = (n0 + n1) + (n2 + n3);
    const float4* ee = (const float4*)(g_EtE + (size_t)k * KP);
    float d0 = 0.f, d1 = 0.f, d2 = 0.f, d3 = 0.f;
    #pragma unroll 8
    for (int i = 0; i < KP / 4; i++) {
        float4 v = ee[i];
        d0 = fmaf(v.x, st1[(4 * i + 0) * 8 + r], d0);
        d1 = fmaf(v.y, st1[(4 * i + 1) * 8 + r], d1);
        d2 = fmaf(v.z, st1[(4 * i + 2) * 8 + r], d2);
        d3 = fmaf(v.w, st1[(4 * i + 3) * 8 + r], d3);
    }
    float den = (d0 + d1) + (d2 + d3);
    g_bases[b * KPR + idx] *= num / (den + EPSV);
}

// ---------------- final coef update + reconstruction ----------------
__global__ __launch_bounds__(NTF) void k_final(const float* __restrict__ x,
                                               float* __restrict__ out) {
    __shared__ __align__(16) float ebs[DR];
    __shared__ float gs[64];
    int t = threadIdx.x, blk = blockIdx.x, b = blockIdx.y;
    int n0 = blk * NTF;
    for (int i = t; i < DR; i += NTF)
        ebs[i] = g_ebp[b * DR + i] + g_ebp[(Bb + b) * DR + i];
    __syncthreads();
    if (t < 64) {
        int r = t >> 3, s = t & 7;
        float a = 0.f;
        #pragma unroll 8
        for (int d = 0; d < Dd; d++) a = fmaf(ebs[d * 8 + r], ebs[d * 8 + s], a);
        gs[t] = a;
    }

    const float* xb = x + (size_t)b * DN + n0 + t;
    unsigned long long L2a[4] = {0ull, 0ull, 0ull, 0ull};
    #pragma unroll 1
    for (int d0 = 0; d0 < Dd; d0 += 16) {
        float xv[16];
        #pragma unroll
        for (int i = 0; i < 16; i++) xv[i] = __ldg(xb + (size_t)(d0 + i) * Nn);
        #pragma unroll
        for (int i = 0; i < 16; i++) {
            unsigned long long x2 = pk2(xv[i], xv[i]);
            const ulonglong2* ep = (const ulonglong2*)(ebs + (d0 + i) * 8);
            ulonglong2 e0 = ep[0], e1 = ep[1];
            L2a[0] = fma2_(x2, e0.x, L2a[0]);
            L2a[1] = fma2_(x2, e0.y, L2a[1]);
            L2a[2] = fma2_(x2, e1.x, L2a[2]);
            L2a[3] = fma2_(x2, e1.y, L2a[3]);
        }
    }
    __syncthreads();

    float L[8];
    upk2(L2a[0], L[0], L[1]); upk2(L2a[1], L[2], L[3]);
    upk2(L2a[2], L[4], L[5]); upk2(L2a[3], L[6], L[7]);

    int n = n0 + t;
    const float4* cg = (const float4*)(g_coef + ((size_t)b * Nn + n) * 8);
    float4 a = cg[0], c = cg[1];
    float c_old[8] = {a.x, a.y, a.z, a.w, c.x, c.y, c.z, c.w};

    float c1[8];
    #pragma unroll
    for (int r = 0; r < 8; r++) {
        float den = 0.f;
        #pragma unroll
        for (int s = 0; s < 8; s++) den = fmaf(c_old[s], gs[s * 8 + r], den);
        c1[r] = c_old[r] * L[r] / (den + EPSV);
    }

    float* ob = out + (size_t)b * DN + n0 + t;
    #pragma unroll 4
    for (int d = 0; d < Dd; d++) {
        const float4* ep = (const float4*)(ebs + d * 8);
        float4 e0 = ep[0], e1 = ep[1];
        float v = e0.x * c1[0] + e0.y * c1[1] + e0.z * c1[2] + e0.w * c1[3]
                + e1.x * c1[4] + e1.y * c1[5] + e1.z * c1[6] + e1.w * c1[7];
        ob[(size_t)d * Nn] = v;
    }
}

// ---------------- launch ----------------
extern "C" void kernel_launch(void* const* d_in, const int* in_sizes, int n_in,
                              void* d_out, int out_size) {
    const float* x = (const float*)d_in[0];
    const float* binit = (const float*)d_in[1];
    float* out = (float*)d_out;

    const int PS = (Dd * XSS + Rr * CTS + DR + 64) * (int)sizeof(float);
    cudaFuncSetAttribute(k_pass<1>, cudaFuncAttributeMaxDynamicSharedMemorySize, PS);
    cudaFuncSetAttribute(k_pass<0>, cudaFuncAttributeMaxDynamicSharedMemorySize, PS);

    // Launch order keeps k_pass<1> at ncu snapshot index 3.
    k_build_E<<<Dd, 256>>>();                       // 0
    k_norm<<<Bb, 256>>>(binit);                     // 1
    k_EbG2<<<dim3(40, 2, Bb), 256>>>();             // 2
    k_pass<1><<<dim3(NBLK, Bb), NT, PS>>>(x);       // 3  <- profiled
    k_EtE<<<148, 256>>>();                          // 4
    k_glueA<<<dim3(6, Bb), 256>>>();
    k_glueB<<<dim3(19, Bb), 256>>>();
    k_EbG2<<<dim3(40, 2, Bb), 256>>>();

    for (int s = 1; s < 4; s++) {
        k_pass<0><<<dim3(NBLK, Bb), NT, PS>>>(x);
        k_glueA<<<dim3(6, Bb), 256>>>();
        k_glueB<<<dim3(19, Bb), 256>>>();
        k_EbG2<<<dim3(40, 2, Bb), 256>>>();
    }
    k_final<<<dim3(NBLKF, Bb), NTF>>>(x, out);
}

// round 8
// speedup vs baseline: 1.0684x; 1.0027x over previous
#include <cuda_runtime.h>
#include <math.h>

#define Bb   8
#define Dd   160
#define Nn   32768
#define Kk   589
#define KP   592                 // padded K (float4-aligned, pads are zero)
#define KPR  (KP * 8)            // padded bases/t1 batch stride
#define Rr   8
#define EPSV 1e-6f
#define DN   ((size_t)Dd * (size_t)Nn)
#define KR   (Kk * Rr)           // 4712
#define DR   (Dd * Rr)           // 1280
#define NSLAB 1024               // k_xc n-slab
#define NXBLK 32                 // Nn / NSLAB
#define CTS2  1044               // ct row stride (words): 8B-aligned, conflict-free
#define NTF  256
#define NBLKF 128

// ---------------- static device scratch ----------------
__device__ float g_E    [Dd * KP];
__device__ float g_Et   [Kk * Dd];
__device__ float g_EtE  [(size_t)Kk * KP];
__device__ float g_bases[Bb * KPR];
__device__ float g_t1   [Bb * KPR];
__device__ float g_ebp  [2 * Bb * DR];              // Eb split-K partials
__device__ float g_coef [(size_t)Bb * Nn * Rr];
__device__ float g_sxc  [(size_t)Bb * NXBLK * DR];
__device__ float g_sctc [Bb * NXBLK * 64];
__device__ float g_xcoef[Bb * DR];

// ---------------- packed f32x2 helpers ----------------
__device__ __forceinline__ unsigned long long pk2(float lo, float hi) {
    unsigned long long r;
    asm("mov.b64 %0, {%1, %2};" : "=l"(r) : "f"(lo), "f"(hi));
    return r;
}
__device__ __forceinline__ void upk2(unsigned long long v, float& lo, float& hi) {
    asm("mov.b64 {%0, %1}, %2;" : "=f"(lo), "=f"(hi) : "l"(v));
}
__device__ __forceinline__ unsigned long long fma2_(unsigned long long a,
                                                    unsigned long long b,
                                                    unsigned long long c) {
    unsigned long long d;
    asm("fma.rn.f32x2 %0, %1, %2, %3;" : "=l"(d) : "l"(a), "l"(b), "l"(c));
    return d;
}

// ---------------- build RBF estimator bank (+ transpose) ----------------
__global__ void k_build_E() {
    int d = blockIdx.x;
    for (int k = threadIdx.x; k < KP; k += blockDim.x) {
        float v = 0.f;
        if (k < Kk) {
            if (k == 588) {
                v = 1.0f;
            } else {
                float sig; int n;
                if      (k < 160) { sig = 6.0f;  n = k; }
                else if (k < 320) { sig = 8.0f;  n = k - 160; }
                else if (k < 400) { sig = 12.0f; n = (k - 320) * 2; }
                else if (k < 480) { sig = 15.0f; n = (k - 400) * 2; }
                else if (k < 534) { sig = 18.0f; n = (k - 480) * 3; }
                else              { sig = 24.0f; n = (k - 534) * 3; }
                float diff = (float)d - (float)n;
                v = expf(-0.5f * (diff * diff) / (2.0f * sig * sig));
            }
        }
        g_E[d * KP + k] = v;
        if (k < Kk) g_Et[k * Dd + d] = v;
    }
}

// ---------------- EtE = E^T E : grid(148), 4 rows/block ----------------
__global__ __launch_bounds__(256) void k_EtE() {
    __shared__ float se[Dd * 4];
    int i0 = blockIdx.x * 4;
    int t = threadIdx.x;
    for (int idx = t; idx < Dd * 4; idx += 256) {
        int d = idx >> 2, i = idx & 3;
        int ki = i0 + i;
        se[idx] = (ki < Kk) ? g_Et[ki * Dd + d] : 0.f;
    }
    __syncthreads();
    int j0 = t, j1 = t + 256, j2 = t + 512;
    bool has2 = (j2 < KP);
    float a0[4] = {0,0,0,0}, a1[4] = {0,0,0,0}, a2[4] = {0,0,0,0};
    #pragma unroll 4
    for (int d = 0; d < Dd; d++) {
        float e0 = g_E[d * KP + j0];
        float e1 = g_E[d * KP + j1];
        float e2 = has2 ? g_E[d * KP + j2] : 0.f;
        #pragma unroll
        for (int i = 0; i < 4; i++) {
            float s = se[d * 4 + i];
            a0[i] = fmaf(e0, s, a0[i]);
            a1[i] = fmaf(e1, s, a1[i]);
            a2[i] = fmaf(e2, s, a2[i]);
        }
    }
    #pragma unroll
    for (int i = 0; i < 4; i++) {
        int row = i0 + i;
        if (row < Kk) {
            g_EtE[(size_t)row * KP + j0] = a0[i];
            g_EtE[(size_t)row * KP + j1] = a1[i];
            if (has2) g_EtE[(size_t)row * KP + j2] = a2[i];
        }
    }
}

// ---------------- L2-normalize bases_init (+ zero pads) ----------------
__global__ void k_norm(const float* __restrict__ bin) {
    int b = blockIdx.x;
    int r = threadIdx.x >> 5;
    int l = threadIdx.x & 31;
    float ss = 0.f;
    for (int k = l; k < Kk; k += 32) {
        float v = bin[(b * Kk + k) * Rr + r];
        ss += v * v;
    }
    #pragma unroll
    for (int o = 16; o; o >>= 1) ss += __shfl_xor_sync(0xffffffffu, ss, o);
    float nrm = fmaxf(sqrtf(ss), 1e-12f);
    for (int k = l; k < Kk; k += 32)
        g_bases[b * KPR + k * Rr + r] = bin[(b * Kk + k) * Rr + r] / nrm;
    if (threadIdx.x < KPR - KR)
        g_bases[b * KPR + KR + threadIdx.x] = 0.f;
}

// ---------------- Eb partials: grid(40, 2, Bb), 8 lanes per output ----------------
__global__ __launch_bounds__(256) void k_EbG2() {
    int t = threadIdx.x;
    int q = blockIdx.y, b = blockIdx.z;
    int out = t >> 3, kg = t & 7;
    int idx = blockIdx.x * 32 + out;               // 0..1279
    int d = idx >> 3, r = idx & 7;
    const float* Erow = g_E + d * KP + q * 296 + kg;
    const float* brow = g_bases + b * KPR + (q * 296 + kg) * 8 + r;
    float acc0 = 0.f, acc1 = 0.f;
    #pragma unroll
    for (int i = 0; i < 36; i += 2) {
        acc0 = fmaf(Erow[8 * i],       brow[64 * i],       acc0);
        acc1 = fmaf(Erow[8 * (i + 1)], brow[64 * (i + 1)], acc1);
    }
    acc0 = fmaf(Erow[8 * 36], brow[64 * 36], acc0);
    float acc = acc0 + acc1;
    acc += __shfl_down_sync(0xffffffffu, acc, 4);
    acc += __shfl_down_sync(0xffffffffu, acc, 2);
    acc += __shfl_down_sync(0xffffffffu, acc, 1);
    if (kg == 0) g_ebp[(q * Bb + b) * DR + idx] = acc;
}

// ---------------- k_num: streaming coef update (no smem tile) ----------------
template<int INIT>
__global__ __launch_bounds__(256) void k_num(const float* __restrict__ x) {
    __shared__ __align__(16) float ebs[DR];
    __shared__ float gs[64];
    int t = threadIdx.x, blk = blockIdx.x, b = blockIdx.y;
    int n0 = blk * 256;
    for (int i = t; i < DR; i += 256)
        ebs[i] = g_ebp[b * DR + i] + g_ebp[(Bb + b) * DR + i];
    __syncthreads();
    if (t < 64) {
        int r = t >> 3, s = t & 7;
        float a = 0.f;
        #pragma unroll 8
        for (int d = 0; d < Dd; d++) a = fmaf(ebs[d * 8 + r], ebs[d * 8 + s], a);
        gs[t] = a;
    }

    const float* xb = x + (size_t)b * DN + n0 + t;
    unsigned long long L2a[4] = {0ull, 0ull, 0ull, 0ull};
    #pragma unroll 1
    for (int d0 = 0; d0 < Dd; d0 += 16) {
        float xv[16];
        #pragma unroll
        for (int i = 0; i < 16; i++) xv[i] = __ldg(xb + (size_t)(d0 + i) * Nn);
        #pragma unroll
        for (int i = 0; i < 16; i++) {
            unsigned long long x2 = pk2(xv[i], xv[i]);
            const ulonglong2* ep = (const ulonglong2*)(ebs + (d0 + i) * 8);
            ulonglong2 e0 = ep[0], e1 = ep[1];
            L2a[0] = fma2_(x2, e0.x, L2a[0]);
            L2a[1] = fma2_(x2, e0.y, L2a[1]);
            L2a[2] = fma2_(x2, e1.x, L2a[2]);
            L2a[3] = fma2_(x2, e1.y, L2a[3]);
        }
    }
    __syncthreads();   // gs visible

    float L[8];
    upk2(L2a[0], L[0], L[1]); upk2(L2a[1], L[2], L[3]);
    upk2(L2a[2], L[4], L[5]); upk2(L2a[3], L[6], L[7]);

    int n = n0 + t;
    float c_old[8];
    if (INIT) {
        float m = L[0];
        #pragma unroll
        for (int i = 1; i < 8; i++) m = fmaxf(m, L[i]);
        float ps = 0.f;
        #pragma unroll
        for (int i = 0; i < 8; i++) { c_old[i] = expf(L[i] - m); ps += c_old[i]; }
        float inv = 1.0f / ps;
        #pragma unroll
        for (int i = 0; i < 8; i++) c_old[i] *= inv;
    } else {
        const float4* cg = (const float4*)(g_coef + ((size_t)b * Nn + n) * 8);
        float4 a = cg[0], c = cg[1];
        c_old[0]=a.x; c_old[1]=a.y; c_old[2]=a.z; c_old[3]=a.w;
        c_old[4]=c.x; c_old[5]=c.y; c_old[6]=c.z; c_old[7]=c.w;
    }

    float c1[8];
    #pragma unroll
    for (int r = 0; r < 8; r++) {
        float den = 0.f;
        #pragma unroll
        for (int s = 0; s < 8; s++) den = fmaf(c_old[s], gs[s * 8 + r], den);
        c1[r] = c_old[r] * L[r] / (den + EPSV);
    }
    float4* cgw = (float4*)(g_coef + ((size_t)b * Nn + n) * 8);
    cgw[0] = make_float4(c1[0], c1[1], c1[2], c1[3]);
    cgw[1] = make_float4(c1[4], c1[5], c1[6], c1[7]);
}

// ---------------- k_xc: x@coef + ctc partials over 1024-n slab ----------------
__global__ __launch_bounds__(256) void k_xc(const float* __restrict__ x) {
    __shared__ __align__(16) float ct[Rr * CTS2];   // 33.4 KB -> ~6 CTAs/SM
    int t = threadIdx.x, blk = blockIdx.x, b = blockIdx.y;
    int n0 = blk * NSLAB;

    // stage coef transposed
    #pragma unroll
    for (int i = 0; i < 4; i++) {
        int nn = i * 256 + t;
        const float4* cg = (const float4*)(g_coef + ((size_t)b * Nn + n0 + nn) * 8);
        float4 a = cg[0], c = cg[1];
        ct[0*CTS2+nn]=a.x; ct[1*CTS2+nn]=a.y; ct[2*CTS2+nn]=a.z; ct[3*CTS2+nn]=a.w;
        ct[4*CTS2+nn]=c.x; ct[5*CTS2+nn]=c.y; ct[6*CTS2+nn]=c.z; ct[7*CTS2+nn]=c.w;
    }
    __syncthreads();

    int p  = t & 3;                  // r-pair: r = 2p, 2p+1
    int dq = t >> 2;                 // 0..63
    bool has2 = (dq < 32);           // warp-uniform
    const float* xb  = x + (size_t)b * DN + n0;
    const float* xr0 = xb + (size_t)dq * Nn;
    const float* xr1 = xb + (size_t)(dq + 64) * Nn;
    const float* xr2 = xb + (size_t)(has2 ? dq + 128 : dq) * Nn;
    const unsigned long long* c0p = (const unsigned long long*)(ct + (2 * p)     * CTS2);
    const unsigned long long* c1p = (const unsigned long long*)(ct + (2 * p + 1) * CTS2);

    unsigned long long aA0=0,aB0=0,aA1=0,aB1=0,aA2=0,aB2=0;
    #pragma unroll 4
    for (int n4 = 0; n4 < NSLAB / 4; n4++) {
        ulonglong2 c0  = *(const ulonglong2*)(c0p + n4 * 2);
        ulonglong2 c1v = *(const ulonglong2*)(c1p + n4 * 2);
        ulonglong2 x0  = *(const ulonglong2*)(xr0 + n4 * 4);
        ulonglong2 x1  = *(const ulonglong2*)(xr1 + n4 * 4);
        aA0 = fma2_(x0.x, c0.x,  aA0); aA0 = fma2_(x0.y, c0.y,  aA0);
        aB0 = fma2_(x0.x, c1v.x, aB0); aB0 = fma2_(x0.y, c1v.y, aB0);
        aA1 = fma2_(x1.x, c0.x,  aA1); aA1 = fma2_(x1.y, c0.y,  aA1);
        aB1 = fma2_(x1.x, c1v.x, aB1); aB1 = fma2_(x1.y, c1v.y, aB1);
        if (has2) {
            ulonglong2 x2 = *(const ulonglong2*)(xr2 + n4 * 4);
            aA2 = fma2_(x2.x, c0.x,  aA2); aA2 = fma2_(x2.y, c0.y,  aA2);
            aB2 = fma2_(x2.x, c1v.x, aB2); aB2 = fma2_(x2.y, c1v.y, aB2);
        }
    }
    float* outp = g_sxc + (size_t)(b * NXBLK + blk) * DR;
    {
        float la, ha, lb, hb;
        upk2(aA0, la, ha); upk2(aB0, lb, hb);
        *(float2*)(outp + dq * 8 + 2 * p) = make_float2(la + ha, lb + hb);
        upk2(aA1, la, ha); upk2(aB1, lb, hb);
        *(float2*)(outp + (dq + 64) * 8 + 2 * p) = make_float2(la + ha, lb + hb);
        if (has2) {
            upk2(aA2, la, ha); upk2(aB2, lb, hb);
            *(float2*)(outp + (dq + 128) * 8 + 2 * p) = make_float2(la + ha, lb + hb);
        }
    }

    // ctc partials (threads 0..63)
    if (t < 64) {
        int r = t >> 3, s = t & 7;
        const unsigned long long* rp = (const unsigned long long*)(ct + r * CTS2);
        const unsigned long long* sp = (const unsigned long long*)(ct + s * CTS2);
        unsigned long long a2 = 0ull, b2 = 0ull;
        #pragma unroll 4
        for (int i = 0; i < NSLAB / 4; i++) {
            a2 = fma2_(rp[2 * i],     sp[2 * i],     a2);
            b2 = fma2_(rp[2 * i + 1], sp[2 * i + 1], b2);
        }
        float lo, hi, lo2, hi2;
        upk2(a2, lo, hi); upk2(b2, lo2, hi2);
        g_sctc[(size_t)(b * NXBLK + blk) * 64 + t] = (lo + hi) + (lo2 + hi2);
    }
}

// ---------------- glue A: grid(6,B). bx<5: reduce x@coef; bx==5: ctc + t1 ----------------
__global__ void k_glueA() {
    __shared__ float sc[64];
    __shared__ float spart[256];
    int bx = blockIdx.x, b = blockIdx.y, t = threadIdx.x;
    if (bx < 5) {
        int o = bx * 256 + t;
        const float* p = g_sxc + (size_t)b * NXBLK * DR + o;
        float a0 = 0, a1 = 0, a2 = 0, a3 = 0;
        #pragma unroll
        for (int blk = 0; blk < NXBLK; blk += 4) {
            a0 += p[(size_t)(blk + 0) * DR];
            a1 += p[(size_t)(blk + 1) * DR];
            a2 += p[(size_t)(blk + 2) * DR];
            a3 += p[(size_t)(blk + 3) * DR];
        }
        g_xcoef[b * DR + o] = (a0 + a1) + (a2 + a3);
        return;
    }
    {
        int o = t & 63, q = t >> 6;
        const float* p = g_sctc + (size_t)b * NXBLK * 64 + o;
        float acc = 0.f;
        #pragma unroll
        for (int blk = q * 8; blk < q * 8 + 8; blk++) acc += p[blk * 64];
        spart[t] = acc;
    }
    __syncthreads();
    if (t < 64) sc[t] = (spart[t] + spart[t + 64]) + (spart[t + 128] + spart[t + 192]);
    __syncthreads();
    const float* bs = g_bases + b * KPR;
    float* t1 = g_t1 + b * KPR;
    for (int idx = t; idx < KR; idx += 256) {
        int k = idx >> 3, r = idx & 7;
        float a = 0.f;
        #pragma unroll
        for (int s = 0; s < 8; s++) a = fmaf(bs[k * 8 + s], sc[s * 8 + r], a);
        t1[idx] = a;
    }
}

// ---------------- glue B: bases *= (E^T xcoef) / (EtE @ t1 + eps) ----------------
__global__ __launch_bounds__(256) void k_glueB() {
    __shared__ float sx[DR];
    __shared__ __align__(16) float st1[KP * Rr];
    int b = blockIdx.y, t = threadIdx.x;
    for (int i = t; i < DR; i += 256) sx[i] = g_xcoef[b * DR + i];
    for (int i = t; i < KP * Rr; i += 256) st1[i] = g_t1[b * KPR + i];
    __syncthreads();
    int idx = blockIdx.x * 256 + t;
    if (idx >= KR) return;
    int k = idx >> 3, r = idx & 7;
    const float4* et = (const float4*)(g_Et + k * Dd);
    float n0 = 0.f, n1 = 0.f, n2 = 0.f, n3 = 0.f;
    #pragma unroll 8
    for (int i = 0; i < Dd / 4; i++) {
        float4 e = et[i];
        n0 = fmaf(e.x, sx[(4 * i + 0) * 8 + r], n0);
        n1 = fmaf(e.y, sx[(4 * i + 1) * 8 + r], n1);
        n2 = fmaf(e.z, sx[(4 * i + 2) * 8 + r], n2);
        n3 = fmaf(e.w, sx[(4 * i + 3) * 8 + r], n3);
    }
    float num = (n0 + n1) + (n2 + n3);
    const float4* ee = (const float4*)(g_EtE + (size_t)k * KP);
    float d0 = 0.f, d1 = 0.f, d2 = 0.f, d3 = 0.f;
    #pragma unroll 8
    for (int i = 0; i < KP / 4; i++) {
        float4 v = ee[i];
        d0 = fmaf(v.x, st1[(4 * i + 0) * 8 + r], d0);
        d1 = fmaf(v.y, st1[(4 * i + 1) * 8 + r], d1);
        d2 = fmaf(v.z, st1[(4 * i + 2) * 8 + r], d2);
        d3 = fmaf(v.w, st1[(4 * i + 3) * 8 + r], d3);
    }
    float den = (d0 + d1) + (d2 + d3);
    g_bases[b * KPR + idx] *= num / (den + EPSV);
}

// ---------------- final coef update + reconstruction ----------------
__global__ __launch_bounds__(NTF) void k_final(const float* __restrict__ x,
                                               float* __restrict__ out) {
    __shared__ __align__(16) float ebs[DR];
    __shared__ float gs[64];
    int t = threadIdx.x, blk = blockIdx.x, b = blockIdx.y;
    int n0 = blk * NTF;
    for (int i = t; i < DR; i += NTF)
        ebs[i] = g_ebp[b * DR + i] + g_ebp[(Bb + b) * DR + i];
    __syncthreads();
    if (t < 64) {
        int r = t >> 3, s = t & 7;
        float a = 0.f;
        #pragma unroll 8
        for (int d = 0; d < Dd; d++) a = fmaf(ebs[d * 8 + r], ebs[d * 8 + s], a);
        gs[t] = a;
    }

    const float* xb = x + (size_t)b * DN + n0 + t;
    unsigned long long L2a[4] = {0ull, 0ull, 0ull, 0ull};
    #pragma unroll 1
    for (int d0 = 0; d0 < Dd; d0 += 16) {
        float xv[16];
        #pragma unroll
        for (int i = 0; i < 16; i++) xv[i] = __ldg(xb + (size_t)(d0 + i) * Nn);
        #pragma unroll
        for (int i = 0; i < 16; i++) {
            unsigned long long x2 = pk2(xv[i], xv[i]);
            const ulonglong2* ep = (const ulonglong2*)(ebs + (d0 + i) * 8);
            ulonglong2 e0 = ep[0], e1 = ep[1];
            L2a[0] = fma2_(x2, e0.x, L2a[0]);
            L2a[1] = fma2_(x2, e0.y, L2a[1]);
            L2a[2] = fma2_(x2, e1.x, L2a[2]);
            L2a[3] = fma2_(x2, e1.y, L2a[3]);
        }
    }
    __syncthreads();

    float L[8];
    upk2(L2a[0], L[0], L[1]); upk2(L2a[1], L[2], L[3]);
    upk2(L2a[2], L[4], L[5]); upk2(L2a[3], L[6], L[7]);

    int n = n0 + t;
    const float4* cg = (const float4*)(g_coef + ((size_t)b * Nn + n) * 8);
    float4 a = cg[0], c = cg[1];
    float c_old[8] = {a.x, a.y, a.z, a.w, c.x, c.y, c.z, c.w};

    float c1[8];
    #pragma unroll
    for (int r = 0; r < 8; r++) {
        float den = 0.f;
        #pragma unroll
        for (int s = 0; s < 8; s++) den = fmaf(c_old[s], gs[s * 8 + r], den);
        c1[r] = c_old[r] * L[r] / (den + EPSV);
    }

    float* ob = out + (size_t)b * DN + n0 + t;
    #pragma unroll 4
    for (int d = 0; d < Dd; d++) {
        const float4* ep = (const float4*)(ebs + d * 8);
        float4 e0 = ep[0], e1 = ep[1];
        float v = e0.x * c1[0] + e0.y * c1[1] + e0.z * c1[2] + e0.w * c1[3]
                + e1.x * c1[4] + e1.y * c1[5] + e1.z * c1[6] + e1.w * c1[7];
        ob[(size_t)d * Nn] = v;
    }
}

// ---------------- launch ----------------
extern "C" void kernel_launch(void* const* d_in, const int* in_sizes, int n_in,
                              void* d_out, int out_size) {
    const float* x = (const float*)d_in[0];
    const float* binit = (const float*)d_in[1];
    float* out = (float*)d_out;

    k_build_E<<<Dd, 256>>>();                        // 0
    k_norm<<<Bb, 256>>>(binit);                      // 1
    k_EbG2<<<dim3(40, 2, Bb), 256>>>();              // 2
    k_num<1><<<dim3(Nn / 256, Bb), 256>>>(x);        // 3  <- profiled
    k_xc<<<dim3(NXBLK, Bb), 256>>>(x);               // 4
    k_EtE<<<148, 256>>>();                           // 5
    k_glueA<<<dim3(6, Bb), 256>>>();
    k_glueB<<<dim3(19, Bb), 256>>>();
    k_EbG2<<<dim3(40, 2, Bb), 256>>>();

    for (int s = 1; s < 4; s++) {
        k_num<0><<<dim3(Nn / 256, Bb), 256>>>(x);
        k_xc<<<dim3(NXBLK, Bb), 256>>>(x);
        k_glueA<<<dim3(6, Bb), 256>>>();
        k_glueB<<<dim3(19, Bb), 256>>>();
        k_EbG2<<<dim3(40, 2, Bb), 256>>>();
    }
    k_final<<<dim3(NBLKF, Bb), NTF>>>(x, out);
}